// round 2
// baseline (speedup 1.0000x reference)
#include <cuda_runtime.h>
#include <float.h>
#include <math.h>

// Problem constants: x = [B=16, C=2048, H=48, W=64] fp32
// 21 regions; 6 distinct row ranges built from 6 row segments
// (breakpoints 0,12,16,24,32,36,48 — all multiples of 4).
#define B_  16
#define C_  2048
#define H_  48
#define W_  64
#define NPLANE (B_ * C_)
#define R_  21
#define EPS_ 1e-6f

__device__ float g_vecs[B_ * R_ * C_];    // [b][r][c]

// Row-range index per region:
//  RR0=[0,48) RR1=[0,32) RR2=[16,48) RR3=[0,24) RR4=[12,36) RR5=[24,48)
__constant__ int REG_RR[R_] = {
    0,
    0, 0,
    1, 1, 1,
    2, 2, 2,
    3, 3, 3, 3,
    4, 4, 4, 4,
    5, 5, 5, 5
};
__constant__ int REG_C0[R_] = {
    0,
    0, 16,
    0, 16, 32,
    0, 16, 32,
    0, 13, 26, 40,
    0, 13, 26, 40,
    0, 13, 26, 40
};
__constant__ int REG_C1[R_] = {
    64,
    48, 64,
    32, 48, 64,
    32, 48, 64,
    24, 37, 50, 64,
    24, 37, 50, 64,
    24, 37, 50, 64
};

__device__ __forceinline__ float4 fmax4(float4 a, float4 b) {
    return make_float4(fmaxf(a.x, b.x), fmaxf(a.y, b.y),
                       fmaxf(a.z, b.z), fmaxf(a.w, b.w));
}
__device__ __forceinline__ float4 shflmax4(float4 v, int xorlane) {
    v.x = fmaxf(v.x, __shfl_xor_sync(0xffffffffu, v.x, xorlane));
    v.y = fmaxf(v.y, __shfl_xor_sync(0xffffffffu, v.y, xorlane));
    v.z = fmaxf(v.z, __shfl_xor_sync(0xffffffffu, v.z, xorlane));
    v.w = fmaxf(v.w, __shfl_xor_sync(0xffffffffu, v.w, xorlane));
    return v;
}

// ---------------------------------------------------------------------------
// Kernel 1: one block per (b,c) plane, 64 threads.
// Thread t: quad q = t&15 (columns 4q..4q+3), row phase r0 = t>>4.
// Rows r0 + 4k, k=0..11 -> 12 LDG.128 with immediate offsets.
// Segment of row r0+4k depends only on k (breakpoints are multiples of 4):
//   k=0..2 -> seg0 [0,12); k=3 -> seg1 [12,16); k=4,5 -> seg2 [16,24);
//   k=6,7 -> seg3 [24,32); k=8 -> seg4 [32,36); k=9..11 -> seg5 [36,48).
// ---------------------------------------------------------------------------
__global__ __launch_bounds__(64) void rpool_max_kernel(
    const float* __restrict__ x, float* __restrict__ vecs)
{
    const int plane = blockIdx.x;             // b * C + c
    const int t = threadIdx.x;
    const int q = t & 15;
    const int r0 = t >> 4;
    const float4* __restrict__ p4 =
        reinterpret_cast<const float4*>(x + (size_t)plane * (H_ * W_))
        + (size_t)r0 * 16 + q;
    // row stride = 16 float4; 4-row stride = 64 float4

    float4 s0 = fmax4(fmax4(p4[0],   p4[64]),  p4[128]);
    float4 s1 = p4[192];
    float4 s2 = fmax4(p4[256], p4[320]);
    float4 s3 = fmax4(p4[384], p4[448]);
    float4 s4 = p4[512];
    float4 s5 = fmax4(fmax4(p4[576], p4[640]), p4[704]);

    // combine row phases {0,1} / {2,3} within each warp (r0 ^= 1 is lane ^ 16)
    s0 = shflmax4(s0, 16); s1 = shflmax4(s1, 16); s2 = shflmax4(s2, 16);
    s3 = shflmax4(s3, 16); s4 = shflmax4(s4, 16); s5 = shflmax4(s5, 16);

    // smem: per-warp segment maxes, [warp][seg][64 cols] as floats
    __shared__ float segs[2][6][W_];
    const int warp = t >> 5, lane = t & 31;
    if (lane < 16) {
        reinterpret_cast<float4*>(segs[warp][0])[q] = s0;
        reinterpret_cast<float4*>(segs[warp][1])[q] = s1;
        reinterpret_cast<float4*>(segs[warp][2])[q] = s2;
        reinterpret_cast<float4*>(segs[warp][3])[q] = s3;
        reinterpret_cast<float4*>(segs[warp][4])[q] = s4;
        reinterpret_cast<float4*>(segs[warp][5])[q] = s5;
    }
    __syncthreads();

    // per-column: combine warps, build 6 row-range maxes
    __shared__ float rr[6][W_];
    {
        const int col = t;
        const float c0 = fmaxf(segs[0][0][col], segs[1][0][col]);
        const float c1 = fmaxf(segs[0][1][col], segs[1][1][col]);
        const float c2 = fmaxf(segs[0][2][col], segs[1][2][col]);
        const float c3 = fmaxf(segs[0][3][col], segs[1][3][col]);
        const float c4 = fmaxf(segs[0][4][col], segs[1][4][col]);
        const float c5 = fmaxf(segs[0][5][col], segs[1][5][col]);
        const float m012 = fmaxf(fmaxf(c0, c1), c2);
        const float m345 = fmaxf(fmaxf(c3, c4), c5);
        rr[0][col] = fmaxf(m012, m345);                    // [0,48)
        rr[1][col] = fmaxf(m012, c3);                      // [0,32)
        rr[2][col] = fmaxf(fmaxf(c2, c3), fmaxf(c4, c5));  // [16,48)
        rr[3][col] = m012;                                 // [0,24)
        rr[4][col] = fmaxf(fmaxf(c1, c2), fmaxf(c3, c4));  // [12,36)
        rr[5][col] = m345;                                 // [24,48)
    }
    __syncthreads();

    const int b = plane >> 11;          // / C_
    const int c = plane & (C_ - 1);     // % C_

    for (int reg = warp; reg < R_; reg += 2) {
        const int ri = REG_RR[reg];
        const int cc0 = REG_C0[reg];
        const int cc1 = REG_C1[reg];
        float m = -FLT_MAX;
        for (int cc = cc0 + lane; cc < cc1; cc += 32)
            m = fmaxf(m, rr[ri][cc]);
        #pragma unroll
        for (int o = 16; o > 0; o >>= 1)
            m = fmaxf(m, __shfl_xor_sync(0xffffffffu, m, o));
        if (lane == 0)
            vecs[((size_t)(b * R_ + reg)) * C_ + c] = m;
    }
}

// ---------------------------------------------------------------------------
// Kernel 2 (fused norm + aggregate): one block per batch b, 256 threads.
// Pass 1: 21 per-region L2 norms over C (vecs is L2-resident, 2.75 MB).
// Pass 2: weighted sum over regions, L2-normalize over channels, write out.
// ---------------------------------------------------------------------------
__global__ __launch_bounds__(256) void rpool_normagg_kernel(
    const float* __restrict__ vecs, float* __restrict__ out)
{
    const int b = blockIdx.x;
    const int tid = threadIdx.x;
    const int lane = tid & 31, warp = tid >> 5;
    const float* __restrict__ vb = vecs + (size_t)b * R_ * C_;

    // ---- pass 1: per-region sum of squares ----
    float acc[R_];
    #pragma unroll
    for (int r = 0; r < R_; r++) acc[r] = 0.f;
    #pragma unroll
    for (int r = 0; r < R_; r++) {
        #pragma unroll
        for (int i = 0; i < C_ / 256; i++) {
            const float v = vb[r * C_ + tid + i * 256];
            acc[r] += v * v;
        }
    }
    #pragma unroll
    for (int r = 0; r < R_; r++) {
        #pragma unroll
        for (int o = 16; o > 0; o >>= 1)
            acc[r] += __shfl_xor_sync(0xffffffffu, acc[r], o);
    }
    __shared__ float ws[8][R_];
    if (lane == 0) {
        #pragma unroll
        for (int r = 0; r < R_; r++) ws[warp][r] = acc[r];
    }
    __syncthreads();
    __shared__ float inv[R_];
    if (tid < R_) {
        float s = 0.f;
        #pragma unroll
        for (int w = 0; w < 8; w++) s += ws[w][tid];
        inv[tid] = 1.0f / (sqrtf(s) + EPS_);
    }
    __syncthreads();

    // ---- pass 2: aggregate + global L2 normalize ----
    float sreg[C_ / 256];
    float local = 0.f;
    #pragma unroll
    for (int i = 0; i < C_ / 256; i++) {
        const int c = tid + i * 256;
        float s = 0.f;
        #pragma unroll
        for (int r = 0; r < R_; r++)
            s += vb[r * C_ + c] * inv[r];
        sreg[i] = s;
        local += s * s;
    }

    #pragma unroll
    for (int o = 16; o > 0; o >>= 1)
        local += __shfl_xor_sync(0xffffffffu, local, o);
    __shared__ float wsum[8];
    if (lane == 0) wsum[warp] = local;
    __syncthreads();
    __shared__ float s_invnorm;
    if (warp == 0) {
        float v = (lane < 8) ? wsum[lane] : 0.f;
        #pragma unroll
        for (int o = 4; o > 0; o >>= 1)
            v += __shfl_xor_sync(0xffffffffu, v, o);
        if (lane == 0) s_invnorm = 1.0f / (sqrtf(v) + EPS_);
    }
    __syncthreads();

    const float invn = s_invnorm;
    #pragma unroll
    for (int i = 0; i < C_ / 256; i++) {
        const int c = tid + i * 256;
        out[(size_t)b * C_ + c] = sreg[i] * invn;
    }
}

extern "C" void kernel_launch(void* const* d_in, const int* in_sizes, int n_in,
                              void* d_out, int out_size)
{
    const float* x = (const float*)d_in[0];
    float* out = (float*)d_out;

    float* vecs;
    cudaGetSymbolAddress((void**)&vecs, g_vecs);

    rpool_max_kernel<<<NPLANE, 64>>>(x, vecs);
    rpool_normagg_kernel<<<B_, 256>>>(vecs, out);
}